// round 11
// baseline (speedup 1.0000x reference)
#include <cuda_runtime.h>
#include <cstdint>
#include <math.h>

#define NB 32
#define NT 64
#define NI 64
#define NO 16
#define NH 512
#define ICH 32   // i-chunks per step
#define IPT 16   // i per chunk (NH/ICH)

// ---------------- persistent device state (no allocations allowed) -------------
__device__ float g_Scum[NB*NH*NH];          // cumulative raw syn normals (33.5MB)
__device__ float g_A[(NT+1)*NB*NH];         // a_t = tanh(h_t) history
__device__ float g_h[NB*NH];                // hidden state
__device__ float g_rpart[ICH*NB*NH];        // partials of a^T(whh + cb*Scum)
__device__ unsigned g_keys[NT][4];          // per-step k1,k2 (threefry keys)
__device__ float g_whhT[NH*NH];             // w_hh transposed (i-major)
__device__ float g_winT[NI*NH];             // w_in transposed (k-major)

// ---------------- JAX threefry2x32 (exact) ------------------------------------
__device__ __forceinline__ void tf2x32(unsigned k0, unsigned k1, unsigned x0, unsigned x1,
                                       unsigned &o0, unsigned &o1) {
    unsigned k2 = k0 ^ k1 ^ 0x1BD11BDAu;
    x0 += k0; x1 += k1;
#define TFR(r) { x0 += x1; x1 = __funnelshift_l(x1, x1, r); x1 ^= x0; }
    TFR(13) TFR(15) TFR(26) TFR(6)
    x0 += k1; x1 += k2 + 1u;
    TFR(17) TFR(29) TFR(16) TFR(24)
    x0 += k2; x1 += k0 + 2u;
    TFR(13) TFR(15) TFR(26) TFR(6)
    x0 += k0; x1 += k1 + 3u;
    TFR(17) TFR(29) TFR(16) TFR(24)
    x0 += k1; x1 += k2 + 4u;
    TFR(13) TFR(15) TFR(26) TFR(6)
    x0 += k2; x1 += k0 + 5u;
#undef TFR
    o0 = x0; o1 = x1;
}

// 4 interleaved threefry streams, counters c, c+1, c+2, c+3 — high ILP
__device__ __forceinline__ void tf2x32_x4(unsigned k0, unsigned k1, unsigned k2,
                                          unsigned c, unsigned* bits) {
    unsigned a0 = k0, b0 = k1 + c;
    unsigned a1 = k0, b1 = b0 + 1u;
    unsigned a2 = k0, b2 = b0 + 2u;
    unsigned a3 = k0, b3 = b0 + 3u;
#define TFR4(r) { \
    a0 += b0; b0 = __funnelshift_l(b0, b0, r); b0 ^= a0; \
    a1 += b1; b1 = __funnelshift_l(b1, b1, r); b1 ^= a1; \
    a2 += b2; b2 = __funnelshift_l(b2, b2, r); b2 ^= a2; \
    a3 += b3; b3 = __funnelshift_l(b3, b3, r); b3 ^= a3; }
#define INJ4(ka, kb, n) { \
    a0 += ka; b0 += kb + n; a1 += ka; b1 += kb + n; \
    a2 += ka; b2 += kb + n; a3 += ka; b3 += kb + n; }
    TFR4(13) TFR4(15) TFR4(26) TFR4(6)
    INJ4(k1, k2, 1u)
    TFR4(17) TFR4(29) TFR4(16) TFR4(24)
    INJ4(k2, k0, 2u)
    TFR4(13) TFR4(15) TFR4(26) TFR4(6)
    INJ4(k0, k1, 3u)
    TFR4(17) TFR4(29) TFR4(16) TFR4(24)
    INJ4(k1, k2, 4u)
    TFR4(13) TFR4(15) TFR4(26) TFR4(6)
    INJ4(k2, k0, 5u)
#undef TFR4
#undef INJ4
    bits[0] = a0 ^ b0; bits[1] = a1 ^ b1; bits[2] = a2 ^ b2; bits[3] = a3 ^ b3;
}

// XLA ErfInv (f32, Giles) — common path unconditional, rare (w>=5, P~0.34%) fixup
__device__ __forceinline__ float erfinv_xla(float x) {
    float w = -__logf(fmaf(-x, x, 1.0f));
    float ws = w - 2.5f;
    float p = 2.81022636e-08f;
    p = fmaf(p, ws, 3.43273939e-07f);
    p = fmaf(p, ws, -3.5233877e-06f);
    p = fmaf(p, ws, -4.39150654e-06f);
    p = fmaf(p, ws, 0.00021858087f);
    p = fmaf(p, ws, -0.00125372503f);
    p = fmaf(p, ws, -0.00417768164f);
    p = fmaf(p, ws, 0.246640727f);
    p = fmaf(p, ws, 1.50140941f);
    if (w >= 5.0f) {                       // rare tail — exact XLA big branch
        float wb = sqrtf(w) - 3.0f;
        p = -0.000200214257f;
        p = fmaf(p, wb, 0.000100950558f);
        p = fmaf(p, wb, 0.00134934322f);
        p = fmaf(p, wb, -0.00367342844f);
        p = fmaf(p, wb, 0.00573950773f);
        p = fmaf(p, wb, -0.0076224613f);
        p = fmaf(p, wb, 0.00943887047f);
        p = fmaf(p, wb, 1.00167406f);
        p = fmaf(p, wb, 2.83297682f);
    }
    return p * x;
}

// JAX normal(f32): bit-trick uniform in [-0.99999994, 1), sqrt(2)*erfinv(u).
// Clamp omitted: f >= 0 implies fmaf(f, hi-lo, lo) >= lo exactly under RN.
__device__ __forceinline__ float bits_to_normal(unsigned bits) {
    float f = __uint_as_float((bits >> 9) | 0x3f800000u) - 1.0f;
    float u = fmaf(f, 1.99999994f, -0.99999994f);
    return 1.41421356f * erfinv_xla(u);
}

// ---------------- init: keys, transposes, h/a0 --------------------------------
__global__ void k_init(const float* __restrict__ hidden,
                       const float* __restrict__ w_hh,
                       const float* __restrict__ w_in) {
    int idx = blockIdx.x * blockDim.x + threadIdx.x;
    if (idx < NH*NH) {                       // w_hhT[i][j] = w_hh[j][i]
        int jj = idx / NH, ii = idx % NH;
        g_whhT[ii*NH + jj] = w_hh[idx];
    }
    if (idx < NI*NH) {                       // w_inT[k][j] = w_in[j][k]
        int jj = idx / NI, kk = idx % NI;
        g_winT[kk*NH + jj] = w_in[idx];
    }
    if (idx < NB*NH) {
        float h = hidden[idx];
        g_h[idx] = h;
        g_A[idx] = tanhf(h);                 // a_0
    }
    if (idx < NT) {
        unsigned f0, f1, a0, a1, b0, b1;
        tf2x32(0u, 1234u, 0u, (unsigned)idx, f0, f1);
        tf2x32(f0, f1, 0u, 0u, a0, a1);      // k1 = block(0,0)
        tf2x32(f0, f1, 0u, 1u, b0, b1);      // k2 = block(0,1)
        g_keys[idx][0] = a0; g_keys[idx][1] = a1;
        g_keys[idx][2] = b0; g_keys[idx][3] = b1;
    }
}

// ------- big per-step pass: syn gen + Scum update + a^T(whh + cb*Scum) --------
// float4 per thread (4 consecutive j); grid (NB, 2 j-halves, ICH); block = 64 jt x 4 i_sub.
// Loop pointers/counters strength-reduced. 40 regs -> 6 blocks/SM fits the RF.
template<bool FIRST>
__global__ void __launch_bounds__(256, 6) k_step_big(int t, const float* __restrict__ beta) {
    const int b   = blockIdx.x;              // 0..31
    const int yh  = blockIdx.y;              // 0..1 (j half)
    const int ch  = blockIdx.z;              // 0..ICH-1
    const int i0  = ch * IPT;
    const int tid = threadIdx.x;
    const int i_sub = tid >> 6;              // 0..3
    const int jt  = tid & 63;
    const int j0  = yh * 256 + jt * 4;       // 4 consecutive j per thread

    __shared__ float sa[IPT];
    __shared__ float red[3][64*4];

    if (tid < IPT) sa[tid] = g_A[((size_t)t*NB + b)*NH + i0 + tid];
    __syncthreads();

    const float4 bt4 = *(const float4*)(beta + j0);
    const float cb0 = 0.002f * bt4.x * sqrtf(bt4.x);
    const float cb1 = 0.002f * bt4.y * sqrtf(bt4.y);
    const float cb2 = 0.002f * bt4.z * sqrtf(bt4.z);
    const float cb3 = 0.002f * bt4.w * sqrtf(bt4.w);
    const unsigned kk0 = g_keys[t][2], kk1 = g_keys[t][3];   // k2 (syn)
    const unsigned kk2 = kk0 ^ kk1 ^ 0x1BD11BDAu;

    float acc0 = 0.f, acc1 = 0.f, acc2 = 0.f, acc3 = 0.f;

    const int ib = i0 + i_sub;
    float*       scp = g_Scum + ((size_t)b*NH + ib)*NH + j0;
    const float* wr  = g_whhT + (size_t)ib*NH + j0;
    const float* sap = sa + i_sub;
    unsigned     c   = (unsigned)((b*NH + ib)*NH + j0);
    const unsigned cstep = 4u*NH;

#pragma unroll 1
    for (int ii = 0; ii < IPT/4; ++ii) {
        const float sai = *sap;
        float4 s4;
        if (FIRST) s4 = make_float4(0.f, 0.f, 0.f, 0.f);
        else       s4 = *(const float4*)scp;
        const float4 w4 = *(const float4*)wr;
        unsigned bits[4];
        tf2x32_x4(kk0, kk1, kk2, c, bits);
        float n0 = bits_to_normal(bits[0]);
        float n1 = bits_to_normal(bits[1]);
        float n2 = bits_to_normal(bits[2]);
        float n3 = bits_to_normal(bits[3]);
        acc0 = fmaf(sai, fmaf(cb0, s4.x, w4.x), acc0);   // Scum BEFORE syn update
        acc1 = fmaf(sai, fmaf(cb1, s4.y, w4.y), acc1);
        acc2 = fmaf(sai, fmaf(cb2, s4.z, w4.z), acc2);
        acc3 = fmaf(sai, fmaf(cb3, s4.w, w4.w), acc3);
        s4.x += n0; s4.y += n1; s4.z += n2; s4.w += n3;
        *(float4*)scp = s4;
        scp += cstep; wr += cstep; c += cstep; sap += 4;
    }

    // reduce the 4 i_sub quarters, publish chunk partial
    if (i_sub > 0) {
        float* r = &red[i_sub-1][jt*4];
        r[0] = acc0; r[1] = acc1; r[2] = acc2; r[3] = acc3;
    }
    __syncthreads();
    if (i_sub == 0) {
#pragma unroll
        for (int q = 0; q < 3; ++q) {
            const float* r = &red[q][jt*4];
            acc0 += r[0]; acc1 += r[1]; acc2 += r[2]; acc3 += r[3];
        }
        *(float4*)(g_rpart + ((size_t)ch*NB + b)*NH + j0) =
            make_float4(acc0, acc1, acc2, acc3);
    }
}

// ---------------- small per-step pass: h update + neuron noise -----------------
__global__ void __launch_bounds__(256) k_step_small(
        int t, const float* __restrict__ xsig,
        const float* __restrict__ b_hh, const float* __restrict__ alpha,
        const float* __restrict__ beta, float* __restrict__ out_hl,
        float* __restrict__ out_hidden) {
    const int b = blockIdx.x;                        // 0..31
    const int j = blockIdx.y * 256 + threadIdx.x;    // 0..511
    __shared__ float s_a[NH];
    __shared__ float s_x[NI];
    __shared__ float s_c[NT];

    const unsigned nk0 = g_keys[t][0], nk1 = g_keys[t][1];   // k1 (neuron noise)
    const float* At = &g_A[((size_t)t*NB + b)*NH];
    for (int i = threadIdx.x; i < NH; i += 256) s_a[i] = At[i];
    if (threadIdx.x < NI) s_x[threadIdx.x] = xsig[((size_t)b*NT + t)*NI + threadIdx.x];
    __syncthreads();

    // Hebbian coefficients c_s = a_t . a_s, s < t (8 warps)
    if (t > 0) {
        int w = threadIdx.x >> 5, lane = threadIdx.x & 31;
        for (int s = w; s < t; s += 8) {
            const float* As = &g_A[((size_t)s*NB + b)*NH];
            float d = 0.f;
            for (int i = lane; i < NH; i += 32) d = fmaf(s_a[i], As[i], d);
            for (int m = 16; m; m >>= 1) d += __shfl_xor_sync(0xffffffffu, d, m);
            if (lane == 0) s_c[s] = d;
        }
        __syncthreads();
    }

    // x_t @ w_in^T
    float x0 = 0.f, x1 = 0.f;
#pragma unroll 8
    for (int k = 0; k < NI; k += 2) {
        x0 = fmaf(s_x[k],   g_winT[k*NH + j],     x0);
        x1 = fmaf(s_x[k+1], g_winT[(k+1)*NH + j], x1);
    }
    float xin = x0 + x1;

    // Hebbian part of dj_act
    float hb = 0.f;
    for (int s = 0; s < t; ++s)
        hb = fmaf(s_c[s], g_A[((size_t)s*NB + b)*NH + j], hb);

    // combined a@whhT + cb*(a^T Scum): sum chunk partials
    float comb = 0.f;
#pragma unroll
    for (int ch = 0; ch < ICH; ++ch) comb += g_rpart[((size_t)ch*NB + b)*NH + j];

    float bj = beta[j];
    float tmp = xin + b_hh[j] + comb - bj * hb;
    float al = alpha[j];
    float h = (1.0f - al) * g_h[b*NH + j] + al * tmp;
    if (t >= 16) {
        unsigned o0, o1;
        tf2x32(nk0, nk1, 0u, (unsigned)(b*NH + j), o0, o1);
        h += 0.05f * sqrtf(al) * bits_to_normal(o0 ^ o1);
    }

    g_h[b*NH + j] = h;
    out_hl[((size_t)b*NT + t)*NH + j] = h;
    g_A[((size_t)(t+1)*NB + b)*NH + j] = tanhf(h);
    if (t == NT - 1) out_hidden[b*NH + j] = h;
}

// ---------------- final: output_list GEMM --------------------------------------
__global__ void k_out(const float* __restrict__ w_out,
                      const float* __restrict__ hl,
                      float* __restrict__ out_ol) {
    int idx = blockIdx.x * blockDim.x + threadIdx.x;     // 32*64*16
    if (idx >= NB*NT*NO) return;
    int o = idx & (NO-1);
    int bt = idx >> 4;
    const float* hr = &hl[(size_t)bt*NH];
    const float* wr = &w_out[o*NH];
    float a0 = 0.f, a1 = 0.f;
#pragma unroll 8
    for (int jj = 0; jj < NH; jj += 2) {
        a0 = fmaf(hr[jj],   wr[jj],   a0);
        a1 = fmaf(hr[jj+1], wr[jj+1], a1);
    }
    out_ol[idx] = a0 + a1;
}

// ---------------- final: assemble new_j -----------------------------------------
__global__ void __launch_bounds__(512) k_newj(const float* __restrict__ w_hh,
                                              const float* __restrict__ beta,
                                              float* __restrict__ out_nj) {
    const int b   = blockIdx.x;          // 0..31
    const int it0 = blockIdx.y * 8;      // i tile of 8
    const int j   = threadIdx.x;         // 0..511
    __shared__ float sAi[NT*8];
    for (int v = threadIdx.x; v < NT*8; v += 512) {
        int tt = v >> 3, il = v & 7;
        sAi[v] = g_A[((size_t)tt*NB + b)*NH + it0 + il];
    }
    __syncthreads();
    float acc[8];
#pragma unroll
    for (int il = 0; il < 8; ++il) acc[il] = 0.f;
    for (int tt = 0; tt < NT; ++tt) {
        float aj = g_A[((size_t)tt*NB + b)*NH + j];
#pragma unroll
        for (int il = 0; il < 8; ++il) acc[il] = fmaf(sAi[tt*8 + il], aj, acc[il]);
    }
    float bj = beta[j];
    float cs = 0.002f * sqrtf(bj);
#pragma unroll
    for (int il = 0; il < 8; ++il) {
        int i = it0 + il;
        size_t idx = ((size_t)b*NH + i)*NH + j;
        out_nj[idx] = w_hh[i*NH + j] + bj * fmaf(cs, g_Scum[idx], -acc[il]);
    }
}

// ---------------- host launch ---------------------------------------------------
extern "C" void kernel_launch(void* const* d_in, const int* in_sizes, int n_in,
                              void* d_out, int out_size) {
    (void)in_sizes; (void)n_in; (void)out_size;
    const float* x      = (const float*)d_in[0];
    const float* hidden = (const float*)d_in[1];
    const float* w_in   = (const float*)d_in[2];
    const float* w_hh   = (const float*)d_in[3];
    const float* b_hh   = (const float*)d_in[4];
    const float* w_out  = (const float*)d_in[5];
    const float* alpha  = (const float*)d_in[6];
    const float* beta   = (const float*)d_in[7];

    float* out    = (float*)d_out;
    float* out_hl = out;                         // [32,64,512]
    float* out_ol = out_hl + (size_t)NB*NT*NH;   // [32,64,16]
    float* out_h  = out_ol + (size_t)NB*NT*NO;   // [32,512]
    float* out_nj = out_h  + (size_t)NB*NH;      // [32,512,512]

    k_init<<<1024, 256>>>(hidden, w_hh, w_in);
    for (int t = 0; t < NT; ++t) {
        if (t == 0) k_step_big<true ><<<dim3(NB, 2, ICH), 256>>>(t, beta);
        else        k_step_big<false><<<dim3(NB, 2, ICH), 256>>>(t, beta);
        k_step_small<<<dim3(NB, 2), 256>>>(t, x, b_hh, alpha, beta, out_hl, out_h);
    }
    k_out<<<128, 256>>>(w_out, out_hl, out_ol);
    k_newj<<<dim3(NB, NH/8), 512>>>(w_hh, beta, out_nj);
}

// round 12
// speedup vs baseline: 1.2180x; 1.2180x over previous
#include <cuda_runtime.h>
#include <cstdint>
#include <math.h>

#define NB 32
#define NT 64
#define NI 64
#define NO 16
#define NH 512
#define ICH 32   // i-chunks per step
#define IPT 16   // i per chunk (NH/ICH)

// ---------------- persistent device state (no allocations allowed) -------------
__device__ float g_Scum[NB*NH*NH];          // cumulative raw syn normals (33.5MB)
__device__ float g_A[(NT+1)*NB*NH];         // a_t = tanh(h_t) history
__device__ float g_h[NB*NH];                // hidden state
__device__ float g_rpart[ICH*NB*NH];        // partials of a^T(whh + cb*Scum)
__device__ unsigned g_keys[NT][4];          // per-step k1,k2 (threefry keys)
__device__ float g_whhT[NH*NH];             // w_hh transposed (i-major)
__device__ float g_winT[NI*NH];             // w_in transposed (k-major)

// add via IMAD (fma pipe): d = a*one + b, with runtime `one` ptxas can't fold.
__device__ __forceinline__ unsigned addv(unsigned a, unsigned b, unsigned one) {
    unsigned r;
    asm("mad.lo.u32 %0, %1, %2, %3;" : "=r"(r) : "r"(a), "r"(one), "r"(b));
    return r;
}

// ---------------- JAX threefry2x32 (exact) ------------------------------------
__device__ __forceinline__ void tf2x32(unsigned k0, unsigned k1, unsigned x0, unsigned x1,
                                       unsigned &o0, unsigned &o1) {
    unsigned k2 = k0 ^ k1 ^ 0x1BD11BDAu;
    x0 += k0; x1 += k1;
#define TFR(r) { x0 += x1; x1 = __funnelshift_l(x1, x1, r); x1 ^= x0; }
    TFR(13) TFR(15) TFR(26) TFR(6)
    x0 += k1; x1 += k2 + 1u;
    TFR(17) TFR(29) TFR(16) TFR(24)
    x0 += k2; x1 += k0 + 2u;
    TFR(13) TFR(15) TFR(26) TFR(6)
    x0 += k0; x1 += k1 + 3u;
    TFR(17) TFR(29) TFR(16) TFR(24)
    x0 += k1; x1 += k2 + 4u;
    TFR(13) TFR(15) TFR(26) TFR(6)
    x0 += k2; x1 += k0 + 5u;
#undef TFR
    o0 = x0; o1 = x1;
}

// 4 interleaved threefry streams, counters c..c+3. All adds forced onto the
// fma pipe (IMAD) to balance against SHF/LOP3 on the alu pipe.
__device__ __forceinline__ void tf2x32_x4(unsigned k0, unsigned k1, unsigned k2,
                                          unsigned c, unsigned one, unsigned* bits) {
    const unsigned j1 = k2 + 1u, j2 = k0 + 2u, j3 = k1 + 3u,
                   j4 = k2 + 4u, j5 = k0 + 5u;   // injection constants (loop-invariant)
    unsigned a0 = k0, b0 = k1 + c;
    unsigned a1 = k0, b1 = b0 + 1u;
    unsigned a2 = k0, b2 = b0 + 2u;
    unsigned a3 = k0, b3 = b0 + 3u;
#define TFR4(r) { \
    a0 = addv(a0, b0, one); b0 = __funnelshift_l(b0, b0, r); b0 ^= a0; \
    a1 = addv(a1, b1, one); b1 = __funnelshift_l(b1, b1, r); b1 ^= a1; \
    a2 = addv(a2, b2, one); b2 = __funnelshift_l(b2, b2, r); b2 ^= a2; \
    a3 = addv(a3, b3, one); b3 = __funnelshift_l(b3, b3, r); b3 ^= a3; }
#define INJ4(ka, kbn) { \
    a0 = addv(a0, ka, one); b0 = addv(b0, kbn, one); \
    a1 = addv(a1, ka, one); b1 = addv(b1, kbn, one); \
    a2 = addv(a2, ka, one); b2 = addv(b2, kbn, one); \
    a3 = addv(a3, ka, one); b3 = addv(b3, kbn, one); }
    TFR4(13) TFR4(15) TFR4(26) TFR4(6)
    INJ4(k1, j1)
    TFR4(17) TFR4(29) TFR4(16) TFR4(24)
    INJ4(k2, j2)
    TFR4(13) TFR4(15) TFR4(26) TFR4(6)
    INJ4(k0, j3)
    TFR4(17) TFR4(29) TFR4(16) TFR4(24)
    INJ4(k1, j4)
    TFR4(13) TFR4(15) TFR4(26) TFR4(6)
    INJ4(k2, j5)
#undef TFR4
#undef INJ4
    bits[0] = a0 ^ b0; bits[1] = a1 ^ b1; bits[2] = a2 ^ b2; bits[3] = a3 ^ b3;
}

// XLA ErfInv (f32, Giles) — common path unconditional, rare (w>=5, P~0.34%) fixup
__device__ __forceinline__ float erfinv_xla(float x) {
    float w = -__logf(fmaf(-x, x, 1.0f));
    float ws = w - 2.5f;
    float p = 2.81022636e-08f;
    p = fmaf(p, ws, 3.43273939e-07f);
    p = fmaf(p, ws, -3.5233877e-06f);
    p = fmaf(p, ws, -4.39150654e-06f);
    p = fmaf(p, ws, 0.00021858087f);
    p = fmaf(p, ws, -0.00125372503f);
    p = fmaf(p, ws, -0.00417768164f);
    p = fmaf(p, ws, 0.246640727f);
    p = fmaf(p, ws, 1.50140941f);
    if (w >= 5.0f) {                       // rare tail — exact XLA big branch
        float wb = sqrtf(w) - 3.0f;
        p = -0.000200214257f;
        p = fmaf(p, wb, 0.000100950558f);
        p = fmaf(p, wb, 0.00134934322f);
        p = fmaf(p, wb, -0.00367342844f);
        p = fmaf(p, wb, 0.00573950773f);
        p = fmaf(p, wb, -0.0076224613f);
        p = fmaf(p, wb, 0.00943887047f);
        p = fmaf(p, wb, 1.00167406f);
        p = fmaf(p, wb, 2.83297682f);
    }
    return p * x;
}

// JAX normal(f32): bit-trick uniform in [-0.99999994, 1), sqrt(2)*erfinv(u).
// Clamp omitted: f >= 0 implies fmaf(f, hi-lo, lo) >= lo exactly under RN.
__device__ __forceinline__ float bits_to_normal(unsigned bits) {
    float f = __uint_as_float((bits >> 9) | 0x3f800000u) - 1.0f;
    float u = fmaf(f, 1.99999994f, -0.99999994f);
    return 1.41421356f * erfinv_xla(u);
}

// ---------------- init: keys, transposes, h/a0 --------------------------------
__global__ void k_init(const float* __restrict__ hidden,
                       const float* __restrict__ w_hh,
                       const float* __restrict__ w_in) {
    int idx = blockIdx.x * blockDim.x + threadIdx.x;
    if (idx < NH*NH) {                       // w_hhT[i][j] = w_hh[j][i]
        int jj = idx / NH, ii = idx % NH;
        g_whhT[ii*NH + jj] = w_hh[idx];
    }
    if (idx < NI*NH) {                       // w_inT[k][j] = w_in[j][k]
        int jj = idx / NI, kk = idx % NI;
        g_winT[kk*NH + jj] = w_in[idx];
    }
    if (idx < NB*NH) {
        float h = hidden[idx];
        g_h[idx] = h;
        g_A[idx] = tanhf(h);                 // a_0
    }
    if (idx < NT) {
        unsigned f0, f1, a0, a1, b0, b1;
        tf2x32(0u, 1234u, 0u, (unsigned)idx, f0, f1);
        tf2x32(f0, f1, 0u, 0u, a0, a1);      // k1 = block(0,0)
        tf2x32(f0, f1, 0u, 1u, b0, b1);      // k2 = block(0,1)
        g_keys[idx][0] = a0; g_keys[idx][1] = a1;
        g_keys[idx][2] = b0; g_keys[idx][3] = b1;
    }
}

// ------- big per-step pass: syn gen + Scum update + a^T(whh + cb*Scum) --------
// float4 per thread (4 consecutive j); grid (NB, 2 j-halves, ICH); block = 64 jt x 4 i_sub.
template<bool FIRST>
__global__ void __launch_bounds__(256, 5) k_step_big(int t, const float* __restrict__ beta,
                                                     unsigned one) {
    const int b   = blockIdx.x;              // 0..31
    const int yh  = blockIdx.y;              // 0..1 (j half)
    const int ch  = blockIdx.z;              // 0..ICH-1
    const int i0  = ch * IPT;
    const int tid = threadIdx.x;
    const int i_sub = tid >> 6;              // 0..3
    const int jt  = tid & 63;
    const int j0  = yh * 256 + jt * 4;       // 4 consecutive j per thread

    __shared__ float sa[IPT];
    __shared__ float red[3][64*4];

    if (tid < IPT) sa[tid] = g_A[((size_t)t*NB + b)*NH + i0 + tid];
    __syncthreads();

    const float4 bt4 = *(const float4*)(beta + j0);
    const float cb0 = 0.002f * bt4.x * sqrtf(bt4.x);
    const float cb1 = 0.002f * bt4.y * sqrtf(bt4.y);
    const float cb2 = 0.002f * bt4.z * sqrtf(bt4.z);
    const float cb3 = 0.002f * bt4.w * sqrtf(bt4.w);
    const unsigned kk0 = g_keys[t][2], kk1 = g_keys[t][3];   // k2 (syn)
    const unsigned kk2 = kk0 ^ kk1 ^ 0x1BD11BDAu;

    float acc0 = 0.f, acc1 = 0.f, acc2 = 0.f, acc3 = 0.f;

    const int ib = i0 + i_sub;
    float*       scp = g_Scum + ((size_t)b*NH + ib)*NH + j0;
    const float* wr  = g_whhT + (size_t)ib*NH + j0;
    const float* sap = sa + i_sub;
    unsigned     c   = (unsigned)((b*NH + ib)*NH + j0);
    const unsigned cstep = 4u*NH;

#pragma unroll 1
    for (int ii = 0; ii < IPT/4; ++ii) {
        const float sai = *sap;
        float4 s4;
        if (FIRST) s4 = make_float4(0.f, 0.f, 0.f, 0.f);
        else       s4 = *(const float4*)scp;
        const float4 w4 = *(const float4*)wr;
        unsigned bits[4];
        tf2x32_x4(kk0, kk1, kk2, c, one, bits);
        float n0 = bits_to_normal(bits[0]);
        float n1 = bits_to_normal(bits[1]);
        float n2 = bits_to_normal(bits[2]);
        float n3 = bits_to_normal(bits[3]);
        acc0 = fmaf(sai, fmaf(cb0, s4.x, w4.x), acc0);   // Scum BEFORE syn update
        acc1 = fmaf(sai, fmaf(cb1, s4.y, w4.y), acc1);
        acc2 = fmaf(sai, fmaf(cb2, s4.z, w4.z), acc2);
        acc3 = fmaf(sai, fmaf(cb3, s4.w, w4.w), acc3);
        s4.x += n0; s4.y += n1; s4.z += n2; s4.w += n3;
        *(float4*)scp = s4;
        scp += cstep; wr += cstep; c += cstep; sap += 4;
    }

    // reduce the 4 i_sub quarters, publish chunk partial
    if (i_sub > 0) {
        float* r = &red[i_sub-1][jt*4];
        r[0] = acc0; r[1] = acc1; r[2] = acc2; r[3] = acc3;
    }
    __syncthreads();
    if (i_sub == 0) {
#pragma unroll
        for (int q = 0; q < 3; ++q) {
            const float* r = &red[q][jt*4];
            acc0 += r[0]; acc1 += r[1]; acc2 += r[2]; acc3 += r[3];
        }
        *(float4*)(g_rpart + ((size_t)ch*NB + b)*NH + j0) =
            make_float4(acc0, acc1, acc2, acc3);
    }
}

// ---------------- small per-step pass: h update + neuron noise -----------------
__global__ void __launch_bounds__(256) k_step_small(
        int t, const float* __restrict__ xsig,
        const float* __restrict__ b_hh, const float* __restrict__ alpha,
        const float* __restrict__ beta, float* __restrict__ out_hl,
        float* __restrict__ out_hidden) {
    const int b = blockIdx.x;                        // 0..31
    const int j = blockIdx.y * 256 + threadIdx.x;    // 0..511
    __shared__ float s_a[NH];
    __shared__ float s_x[NI];
    __shared__ float s_c[NT];

    const float* At = &g_A[((size_t)t*NB + b)*NH];
    for (int i = threadIdx.x; i < NH; i += 256) s_a[i] = At[i];
    if (threadIdx.x < NI) s_x[threadIdx.x] = xsig[((size_t)b*NT + t)*NI + threadIdx.x];
    __syncthreads();

    // Hebbian coefficients c_s = a_t . a_s, s < t (8 warps)
    if (t > 0) {
        int w = threadIdx.x >> 5, lane = threadIdx.x & 31;
        for (int s = w; s < t; s += 8) {
            const float* As = &g_A[((size_t)s*NB + b)*NH];
            float d = 0.f;
            for (int i = lane; i < NH; i += 32) d = fmaf(s_a[i], As[i], d);
            for (int m = 16; m; m >>= 1) d += __shfl_xor_sync(0xffffffffu, d, m);
            if (lane == 0) s_c[s] = d;
        }
        __syncthreads();
    }

    // x_t @ w_in^T
    float x0 = 0.f, x1 = 0.f;
#pragma unroll 8
    for (int k = 0; k < NI; k += 2) {
        x0 = fmaf(s_x[k],   g_winT[k*NH + j],     x0);
        x1 = fmaf(s_x[k+1], g_winT[(k+1)*NH + j], x1);
    }
    float xin = x0 + x1;

    // Hebbian part of dj_act
    float hb = 0.f;
    for (int s = 0; s < t; ++s)
        hb = fmaf(s_c[s], g_A[((size_t)s*NB + b)*NH + j], hb);

    // combined a@whhT + cb*(a^T Scum): sum chunk partials
    float comb = 0.f;
#pragma unroll
    for (int ch = 0; ch < ICH; ++ch) comb += g_rpart[((size_t)ch*NB + b)*NH + j];

    float bj = beta[j];
    float tmp = xin + b_hh[j] + comb - bj * hb;
    float al = alpha[j];
    float h = (1.0f - al) * g_h[b*NH + j] + al * tmp;
    if (t >= 16) {
        unsigned o0, o1;
        tf2x32(g_keys[t][0], g_keys[t][1], 0u, (unsigned)(b*NH + j), o0, o1);
        h += 0.05f * sqrtf(al) * bits_to_normal(o0 ^ o1);
    }

    g_h[b*NH + j] = h;
    out_hl[((size_t)b*NT + t)*NH + j] = h;
    g_A[((size_t)(t+1)*NB + b)*NH + j] = tanhf(h);
    if (t == NT - 1) out_hidden[b*NH + j] = h;
}

// ---------------- final: output_list GEMM --------------------------------------
__global__ void k_out(const float* __restrict__ w_out,
                      const float* __restrict__ hl,
                      float* __restrict__ out_ol) {
    int idx = blockIdx.x * blockDim.x + threadIdx.x;     // 32*64*16
    if (idx >= NB*NT*NO) return;
    int o = idx & (NO-1);
    int bt = idx >> 4;
    const float* hr = &hl[(size_t)bt*NH];
    const float* wr = &w_out[o*NH];
    float a0 = 0.f, a1 = 0.f;
#pragma unroll 8
    for (int jj = 0; jj < NH; jj += 2) {
        a0 = fmaf(hr[jj],   wr[jj],   a0);
        a1 = fmaf(hr[jj+1], wr[jj+1], a1);
    }
    out_ol[idx] = a0 + a1;
}

// ---------------- final: assemble new_j -----------------------------------------
__global__ void __launch_bounds__(512) k_newj(const float* __restrict__ w_hh,
                                              const float* __restrict__ beta,
                                              float* __restrict__ out_nj) {
    const int b   = blockIdx.x;          // 0..31
    const int it0 = blockIdx.y * 8;      // i tile of 8
    const int j   = threadIdx.x;         // 0..511
    __shared__ float sAi[NT*8];
    for (int v = threadIdx.x; v < NT*8; v += 512) {
        int tt = v >> 3, il = v & 7;
        sAi[v] = g_A[((size_t)tt*NB + b)*NH + it0 + il];
    }
    __syncthreads();
    float acc[8];
#pragma unroll
    for (int il = 0; il < 8; ++il) acc[il] = 0.f;
    for (int tt = 0; tt < NT; ++tt) {
        float aj = g_A[((size_t)tt*NB + b)*NH + j];
#pragma unroll
        for (int il = 0; il < 8; ++il) acc[il] = fmaf(sAi[tt*8 + il], aj, acc[il]);
    }
    float bj = beta[j];
    float cs = 0.002f * sqrtf(bj);
#pragma unroll
    for (int il = 0; il < 8; ++il) {
        int i = it0 + il;
        size_t idx = ((size_t)b*NH + i)*NH + j;
        out_nj[idx] = w_hh[i*NH + j] + bj * fmaf(cs, g_Scum[idx], -acc[il]);
    }
}

// ---------------- host launch ---------------------------------------------------
extern "C" void kernel_launch(void* const* d_in, const int* in_sizes, int n_in,
                              void* d_out, int out_size) {
    (void)in_sizes; (void)n_in; (void)out_size;
    const float* x      = (const float*)d_in[0];
    const float* hidden = (const float*)d_in[1];
    const float* w_in   = (const float*)d_in[2];
    const float* w_hh   = (const float*)d_in[3];
    const float* b_hh   = (const float*)d_in[4];
    const float* w_out  = (const float*)d_in[5];
    const float* alpha  = (const float*)d_in[6];
    const float* beta   = (const float*)d_in[7];

    float* out    = (float*)d_out;
    float* out_hl = out;                         // [32,64,512]
    float* out_ol = out_hl + (size_t)NB*NT*NH;   // [32,64,16]
    float* out_h  = out_ol + (size_t)NB*NT*NO;   // [32,512]
    float* out_nj = out_h  + (size_t)NB*NH;      // [32,512,512]

    k_init<<<1024, 256>>>(hidden, w_hh, w_in);
    for (int t = 0; t < NT; ++t) {
        if (t == 0) k_step_big<true ><<<dim3(NB, 2, ICH), 256>>>(t, beta, 1u);
        else        k_step_big<false><<<dim3(NB, 2, ICH), 256>>>(t, beta, 1u);
        k_step_small<<<dim3(NB, 2), 256>>>(t, x, b_hh, alpha, beta, out_hl, out_h);
    }
    k_out<<<128, 256>>>(w_out, out_hl, out_ol);
    k_newj<<<dim3(NB, NH/8), 512>>>(w_hh, beta, out_nj);
}

// round 13
// speedup vs baseline: 1.2442x; 1.0215x over previous
#include <cuda_runtime.h>
#include <cstdint>
#include <math.h>

#define NB 32
#define NT 64
#define NI 64
#define NO 16
#define NH 512
#define ICH 32   // i-chunks per step
#define IPT 16   // i per chunk (NH/ICH)

// ---------------- persistent device state (no allocations allowed) -------------
__device__ float g_Scum[NB*NH*NH];          // cumulative raw syn normals (33.5MB)
__device__ float g_A[(NT+1)*NB*NH];         // a_t = tanh(h_t) history
__device__ float g_h[NB*NH];                // hidden state
__device__ float g_rpart[ICH*NB*NH];        // partials of a^T(whh + cb*Scum)
__device__ unsigned g_keys[NT][4];          // per-step k1,k2 (threefry keys)
__device__ float g_whhT[NH*NH];             // w_hh transposed (i-major)
__device__ float g_winT[NI*NH];             // w_in transposed (k-major)

// add via IMAD (fma pipe): d = a*one + b, with runtime `one` ptxas can't fold.
__device__ __forceinline__ unsigned addv(unsigned a, unsigned b, unsigned one) {
    unsigned r;
    asm("mad.lo.u32 %0, %1, %2, %3;" : "=r"(r) : "r"(a), "r"(one), "r"(b));
    return r;
}

// bits >> 9 on the fma pipe: mad.hi.u32(bits, 2^23, 0) = (bits*2^23)>>32 = bits>>9
__device__ __forceinline__ unsigned shr9_fma(unsigned bits) {
    unsigned r;
    asm("mul.hi.u32 %0, %1, %2;" : "=r"(r) : "r"(bits), "r"(1u << 23));
    return r;
}

// ---------------- JAX threefry2x32 (exact) ------------------------------------
__device__ __forceinline__ void tf2x32(unsigned k0, unsigned k1, unsigned x0, unsigned x1,
                                       unsigned &o0, unsigned &o1) {
    unsigned k2 = k0 ^ k1 ^ 0x1BD11BDAu;
    x0 += k0; x1 += k1;
#define TFR(r) { x0 += x1; x1 = __funnelshift_l(x1, x1, r); x1 ^= x0; }
    TFR(13) TFR(15) TFR(26) TFR(6)
    x0 += k1; x1 += k2 + 1u;
    TFR(17) TFR(29) TFR(16) TFR(24)
    x0 += k2; x1 += k0 + 2u;
    TFR(13) TFR(15) TFR(26) TFR(6)
    x0 += k0; x1 += k1 + 3u;
    TFR(17) TFR(29) TFR(16) TFR(24)
    x0 += k1; x1 += k2 + 4u;
    TFR(13) TFR(15) TFR(26) TFR(6)
    x0 += k2; x1 += k0 + 5u;
#undef TFR
    o0 = x0; o1 = x1;
}

// 4 interleaved threefry streams, counters c..c+3. All adds forced onto the
// fma pipe (IMAD) to balance against SHF/LOP3 on the alu pipe.
__device__ __forceinline__ void tf2x32_x4(unsigned k0, unsigned k1, unsigned k2,
                                          unsigned c, unsigned one, unsigned* bits) {
    const unsigned j1 = k2 + 1u, j2 = k0 + 2u, j3 = k1 + 3u,
                   j4 = k2 + 4u, j5 = k0 + 5u;   // injection constants (loop-invariant)
    unsigned a0 = k0, b0 = k1 + c;
    unsigned a1 = k0, b1 = b0 + 1u;
    unsigned a2 = k0, b2 = b0 + 2u;
    unsigned a3 = k0, b3 = b0 + 3u;
#define TFR4(r) { \
    a0 = addv(a0, b0, one); b0 = __funnelshift_l(b0, b0, r); b0 ^= a0; \
    a1 = addv(a1, b1, one); b1 = __funnelshift_l(b1, b1, r); b1 ^= a1; \
    a2 = addv(a2, b2, one); b2 = __funnelshift_l(b2, b2, r); b2 ^= a2; \
    a3 = addv(a3, b3, one); b3 = __funnelshift_l(b3, b3, r); b3 ^= a3; }
#define INJ4(ka, kbn) { \
    a0 = addv(a0, ka, one); b0 = addv(b0, kbn, one); \
    a1 = addv(a1, ka, one); b1 = addv(b1, kbn, one); \
    a2 = addv(a2, ka, one); b2 = addv(b2, kbn, one); \
    a3 = addv(a3, ka, one); b3 = addv(b3, kbn, one); }
    TFR4(13) TFR4(15) TFR4(26) TFR4(6)
    INJ4(k1, j1)
    TFR4(17) TFR4(29) TFR4(16) TFR4(24)
    INJ4(k2, j2)
    TFR4(13) TFR4(15) TFR4(26) TFR4(6)
    INJ4(k0, j3)
    TFR4(17) TFR4(29) TFR4(16) TFR4(24)
    INJ4(k1, j4)
    TFR4(13) TFR4(15) TFR4(26) TFR4(6)
    INJ4(k2, j5)
#undef TFR4
#undef INJ4
    bits[0] = a0 ^ b0; bits[1] = a1 ^ b1; bits[2] = a2 ^ b2; bits[3] = a3 ^ b3;
}

// XLA ErfInv (f32, Giles), with sqrt(2) folded into the coefficients so the
// result is directly sqrt(2)*erfinv(u) (each coeff scaled at compile time;
// deviation <= ~1ulp vs mul-after, far inside the 1e-3 tolerance).
__device__ __forceinline__ float erfinv_sqrt2_xla(float x) {
    float w = -__logf(fmaf(-x, x, 1.0f));
    float ws = w - 2.5f;
    float p = 2.81022636e-08f * 1.41421356237f;
    p = fmaf(p, ws, 3.43273939e-07f * 1.41421356237f);
    p = fmaf(p, ws, -3.5233877e-06f * 1.41421356237f);
    p = fmaf(p, ws, -4.39150654e-06f * 1.41421356237f);
    p = fmaf(p, ws, 0.00021858087f * 1.41421356237f);
    p = fmaf(p, ws, -0.00125372503f * 1.41421356237f);
    p = fmaf(p, ws, -0.00417768164f * 1.41421356237f);
    p = fmaf(p, ws, 0.246640727f * 1.41421356237f);
    p = fmaf(p, ws, 1.50140941f * 1.41421356237f);
    if (w >= 5.0f) {                       // rare tail (P~0.34%) — same folding
        float wb = sqrtf(w) - 3.0f;
        p = -0.000200214257f * 1.41421356237f;
        p = fmaf(p, wb, 0.000100950558f * 1.41421356237f);
        p = fmaf(p, wb, 0.00134934322f * 1.41421356237f);
        p = fmaf(p, wb, -0.00367342844f * 1.41421356237f);
        p = fmaf(p, wb, 0.00573950773f * 1.41421356237f);
        p = fmaf(p, wb, -0.0076224613f * 1.41421356237f);
        p = fmaf(p, wb, 0.00943887047f * 1.41421356237f);
        p = fmaf(p, wb, 1.00167406f * 1.41421356237f);
        p = fmaf(p, wb, 2.83297682f * 1.41421356237f);
    }
    return p * x;
}

// JAX normal(f32): bit-trick uniform in [-0.99999994, 1), sqrt2*erfinv fused.
// Clamp omitted: f >= 0 implies fmaf(f, hi-lo, lo) >= lo exactly under RN.
__device__ __forceinline__ float bits_to_normal(unsigned bits) {
    float f = __uint_as_float(shr9_fma(bits) | 0x3f800000u) - 1.0f;
    float u = fmaf(f, 1.99999994f, -0.99999994f);
    return erfinv_sqrt2_xla(u);
}

// exact-path variant used in init/small kernel (keeps original op order there too)
__device__ __forceinline__ float bits_to_normal_plain(unsigned bits) {
    float f = __uint_as_float((bits >> 9) | 0x3f800000u) - 1.0f;
    float u = fmaf(f, 1.99999994f, -0.99999994f);
    return erfinv_sqrt2_xla(u);
}

// ---------------- init: keys, transposes, h/a0 --------------------------------
__global__ void k_init(const float* __restrict__ hidden,
                       const float* __restrict__ w_hh,
                       const float* __restrict__ w_in) {
    int idx = blockIdx.x * blockDim.x + threadIdx.x;
    if (idx < NH*NH) {                       // w_hhT[i][j] = w_hh[j][i]
        int jj = idx / NH, ii = idx % NH;
        g_whhT[ii*NH + jj] = w_hh[idx];
    }
    if (idx < NI*NH) {                       // w_inT[k][j] = w_in[j][k]
        int jj = idx / NI, kk = idx % NI;
        g_winT[kk*NH + jj] = w_in[idx];
    }
    if (idx < NB*NH) {
        float h = hidden[idx];
        g_h[idx] = h;
        g_A[idx] = tanhf(h);                 // a_0
    }
    if (idx < NT) {
        unsigned f0, f1, a0, a1, b0, b1;
        tf2x32(0u, 1234u, 0u, (unsigned)idx, f0, f1);
        tf2x32(f0, f1, 0u, 0u, a0, a1);      // k1 = block(0,0)
        tf2x32(f0, f1, 0u, 1u, b0, b1);      // k2 = block(0,1)
        g_keys[idx][0] = a0; g_keys[idx][1] = a1;
        g_keys[idx][2] = b0; g_keys[idx][3] = b1;
    }
}

// ------- big per-step pass: syn gen + Scum update + a^T(whh + cb*Scum) --------
// float4 per thread (4 consecutive j); grid (NB, 2 j-halves, ICH); block = 64 jt x 4 i_sub.
template<bool FIRST>
__global__ void __launch_bounds__(256, 6) k_step_big(int t, const float* __restrict__ beta,
                                                     unsigned one) {
    const int b   = blockIdx.x;              // 0..31
    const int yh  = blockIdx.y;              // 0..1 (j half)
    const int ch  = blockIdx.z;              // 0..ICH-1
    const int i0  = ch * IPT;
    const int tid = threadIdx.x;
    const int i_sub = tid >> 6;              // 0..3
    const int jt  = tid & 63;
    const int j0  = yh * 256 + jt * 4;       // 4 consecutive j per thread

    __shared__ float sa[IPT];
    __shared__ float red[3][64*4];

    if (tid < IPT) sa[tid] = g_A[((size_t)t*NB + b)*NH + i0 + tid];
    __syncthreads();

    const float4 bt4 = *(const float4*)(beta + j0);
    const float cb0 = 0.002f * bt4.x * sqrtf(bt4.x);
    const float cb1 = 0.002f * bt4.y * sqrtf(bt4.y);
    const float cb2 = 0.002f * bt4.z * sqrtf(bt4.z);
    const float cb3 = 0.002f * bt4.w * sqrtf(bt4.w);
    const unsigned kk0 = g_keys[t][2], kk1 = g_keys[t][3];   // k2 (syn)
    const unsigned kk2 = kk0 ^ kk1 ^ 0x1BD11BDAu;

    float acc0 = 0.f, acc1 = 0.f, acc2 = 0.f, acc3 = 0.f;

    const int ib = i0 + i_sub;
    float*       scp = g_Scum + ((size_t)b*NH + ib)*NH + j0;
    const float* wr  = g_whhT + (size_t)ib*NH + j0;
    const float* sap = sa + i_sub;
    unsigned     c   = (unsigned)((b*NH + ib)*NH + j0);
    const unsigned cstep = 4u*NH;

#pragma unroll 1
    for (int ii = 0; ii < IPT/4; ++ii) {
        const float sai = *sap;
        float4 s4;
        if (FIRST) s4 = make_float4(0.f, 0.f, 0.f, 0.f);
        else       s4 = *(const float4*)scp;
        const float4 w4 = *(const float4*)wr;
        unsigned bits[4];
        tf2x32_x4(kk0, kk1, kk2, c, one, bits);
        float n0 = bits_to_normal(bits[0]);
        float n1 = bits_to_normal(bits[1]);
        float n2 = bits_to_normal(bits[2]);
        float n3 = bits_to_normal(bits[3]);
        acc0 = fmaf(sai, fmaf(cb0, s4.x, w4.x), acc0);   // Scum BEFORE syn update
        acc1 = fmaf(sai, fmaf(cb1, s4.y, w4.y), acc1);
        acc2 = fmaf(sai, fmaf(cb2, s4.z, w4.z), acc2);
        acc3 = fmaf(sai, fmaf(cb3, s4.w, w4.w), acc3);
        s4.x += n0; s4.y += n1; s4.z += n2; s4.w += n3;
        *(float4*)scp = s4;
        scp += cstep; wr += cstep; c += cstep; sap += 4;
    }

    // reduce the 4 i_sub quarters, publish chunk partial
    if (i_sub > 0) {
        float* r = &red[i_sub-1][jt*4];
        r[0] = acc0; r[1] = acc1; r[2] = acc2; r[3] = acc3;
    }
    __syncthreads();
    if (i_sub == 0) {
#pragma unroll
        for (int q = 0; q < 3; ++q) {
            const float* r = &red[q][jt*4];
            acc0 += r[0]; acc1 += r[1]; acc2 += r[2]; acc3 += r[3];
        }
        *(float4*)(g_rpart + ((size_t)ch*NB + b)*NH + j0) =
            make_float4(acc0, acc1, acc2, acc3);
    }
}

// ---------------- small per-step pass: h update + neuron noise -----------------
__global__ void __launch_bounds__(256) k_step_small(
        int t, const float* __restrict__ xsig,
        const float* __restrict__ b_hh, const float* __restrict__ alpha,
        const float* __restrict__ beta, float* __restrict__ out_hl,
        float* __restrict__ out_hidden) {
    const int b = blockIdx.x;                        // 0..31
    const int j = blockIdx.y * 256 + threadIdx.x;    // 0..511
    __shared__ float s_a[NH];
    __shared__ float s_x[NI];
    __shared__ float s_c[NT];

    const float* At = &g_A[((size_t)t*NB + b)*NH];
    for (int i = threadIdx.x; i < NH; i += 256) s_a[i] = At[i];
    if (threadIdx.x < NI) s_x[threadIdx.x] = xsig[((size_t)b*NT + t)*NI + threadIdx.x];
    __syncthreads();

    // Hebbian coefficients c_s = a_t . a_s, s < t (8 warps)
    if (t > 0) {
        int w = threadIdx.x >> 5, lane = threadIdx.x & 31;
        for (int s = w; s < t; s += 8) {
            const float* As = &g_A[((size_t)s*NB + b)*NH];
            float d = 0.f;
            for (int i = lane; i < NH; i += 32) d = fmaf(s_a[i], As[i], d);
            for (int m = 16; m; m >>= 1) d += __shfl_xor_sync(0xffffffffu, d, m);
            if (lane == 0) s_c[s] = d;
        }
        __syncthreads();
    }

    // x_t @ w_in^T
    float x0 = 0.f, x1 = 0.f;
#pragma unroll 8
    for (int k = 0; k < NI; k += 2) {
        x0 = fmaf(s_x[k],   g_winT[k*NH + j],     x0);
        x1 = fmaf(s_x[k+1], g_winT[(k+1)*NH + j], x1);
    }
    float xin = x0 + x1;

    // Hebbian part of dj_act
    float hb = 0.f;
    for (int s = 0; s < t; ++s)
        hb = fmaf(s_c[s], g_A[((size_t)s*NB + b)*NH + j], hb);

    // combined a@whhT + cb*(a^T Scum): sum chunk partials
    float comb = 0.f;
#pragma unroll
    for (int ch = 0; ch < ICH; ++ch) comb += g_rpart[((size_t)ch*NB + b)*NH + j];

    float bj = beta[j];
    float tmp = xin + b_hh[j] + comb - bj * hb;
    float al = alpha[j];
    float h = (1.0f - al) * g_h[b*NH + j] + al * tmp;
    if (t >= 16) {
        unsigned o0, o1;
        tf2x32(g_keys[t][0], g_keys[t][1], 0u, (unsigned)(b*NH + j), o0, o1);
        h += 0.05f * sqrtf(al) * bits_to_normal_plain(o0 ^ o1);
    }

    g_h[b*NH + j] = h;
    out_hl[((size_t)b*NT + t)*NH + j] = h;
    g_A[((size_t)(t+1)*NB + b)*NH + j] = tanhf(h);
    if (t == NT - 1) out_hidden[b*NH + j] = h;
}

// ---------------- final: output_list GEMM --------------------------------------
__global__ void k_out(const float* __restrict__ w_out,
                      const float* __restrict__ hl,
                      float* __restrict__ out_ol) {
    int idx = blockIdx.x * blockDim.x + threadIdx.x;     // 32*64*16
    if (idx >= NB*NT*NO) return;
    int o = idx & (NO-1);
    int bt = idx >> 4;
    const float* hr = &hl[(size_t)bt*NH];
    const float* wr = &w_out[o*NH];
    float a0 = 0.f, a1 = 0.f;
#pragma unroll 8
    for (int jj = 0; jj < NH; jj += 2) {
        a0 = fmaf(hr[jj],   wr[jj],   a0);
        a1 = fmaf(hr[jj+1], wr[jj+1], a1);
    }
    out_ol[idx] = a0 + a1;
}

// ---------------- final: assemble new_j -----------------------------------------
__global__ void __launch_bounds__(512) k_newj(const float* __restrict__ w_hh,
                                              const float* __restrict__ beta,
                                              float* __restrict__ out_nj) {
    const int b   = blockIdx.x;          // 0..31
    const int it0 = blockIdx.y * 8;      // i tile of 8
    const int j   = threadIdx.x;         // 0..511
    __shared__ float sAi[NT*8];
    for (int v = threadIdx.x; v < NT*8; v += 512) {
        int tt = v >> 3, il = v & 7;
        sAi[v] = g_A[((size_t)tt*NB + b)*NH + it0 + il];
    }
    __syncthreads();
    float acc[8];
#pragma unroll
    for (int il = 0; il < 8; ++il) acc[il] = 0.f;
    for (int tt = 0; tt < NT; ++tt) {
        float aj = g_A[((size_t)tt*NB + b)*NH + j];
#pragma unroll
        for (int il = 0; il < 8; ++il) acc[il] = fmaf(sAi[tt*8 + il], aj, acc[il]);
    }
    float bj = beta[j];
    float cs = 0.002f * sqrtf(bj);
#pragma unroll
    for (int il = 0; il < 8; ++il) {
        int i = it0 + il;
        size_t idx = ((size_t)b*NH + i)*NH + j;
        out_nj[idx] = w_hh[i*NH + j] + bj * fmaf(cs, g_Scum[idx], -acc[il]);
    }
}

// ---------------- host launch ---------------------------------------------------
extern "C" void kernel_launch(void* const* d_in, const int* in_sizes, int n_in,
                              void* d_out, int out_size) {
    (void)in_sizes; (void)n_in; (void)out_size;
    const float* x      = (const float*)d_in[0];
    const float* hidden = (const float*)d_in[1];
    const float* w_in   = (const float*)d_in[2];
    const float* w_hh   = (const float*)d_in[3];
    const float* b_hh   = (const float*)d_in[4];
    const float* w_out  = (const float*)d_in[5];
    const float* alpha  = (const float*)d_in[6];
    const float* beta   = (const float*)d_in[7];

    float* out    = (float*)d_out;
    float* out_hl = out;                         // [32,64,512]
    float* out_ol = out_hl + (size_t)NB*NT*NH;   // [32,64,16]
    float* out_h  = out_ol + (size_t)NB*NT*NO;   // [32,512]
    float* out_nj = out_h  + (size_t)NB*NH;      // [32,512,512]

    k_init<<<1024, 256>>>(hidden, w_hh, w_in);
    for (int t = 0; t < NT; ++t) {
        if (t == 0) k_step_big<true ><<<dim3(NB, 2, ICH), 256>>>(t, beta, 1u);
        else        k_step_big<false><<<dim3(NB, 2, ICH), 256>>>(t, beta, 1u);
        k_step_small<<<dim3(NB, 2), 256>>>(t, x, b_hh, alpha, beta, out_hl, out_h);
    }
    k_out<<<128, 256>>>(w_out, out_hl, out_ol);
    k_newj<<<dim3(NB, NH/8), 512>>>(w_hh, beta, out_nj);
}